// round 4
// baseline (speedup 1.0000x reference)
#include <cuda_runtime.h>
#include <cstdint>

// Problem constants (fixed shapes from reference)
#define DIM      64
#define KCODES   8192
#define NPTS     32768
#define TN       64          // points per block
#define THREADS  128
#define NTILES   32          // k-tiles of 256 codes

// Codebook re-laid-out as [k/16][d][16]: each 16-code group is a contiguous
// 4KB stream over d. +16 floats pad for the d=64 overfetch of the last group.
__device__ float d_cbT[DIM * KCODES + 16];
// ||c_k||^2 with reference rounding (sequential mul-then-add, no FMA)
__device__ float d_cn[KCODES];

__device__ __forceinline__ void fma2(unsigned long long& d,
                                     unsigned long long a,
                                     unsigned long long b) {
    asm("fma.rn.f32x2 %0, %1, %2, %3;" : "=l"(d) : "l"(a), "l"(b), "l"(d));
}
__device__ __forceinline__ void unpack2(unsigned long long v, float& lo, float& hi) {
    asm("mov.b64 {%0, %1}, %2;" : "=f"(lo), "=f"(hi) : "l"(v));
}

// ---------------------------------------------------------------------------
// prep: transpose codebook into d_cbT ([k/16][d][16]) + compute d_cn.
// One block per 64 codes. Tiny (2 MB moved once).
// ---------------------------------------------------------------------------
__global__ void __launch_bounds__(256) prep_kernel(const float* __restrict__ cb) {
    __shared__ float ts[DIM][65];   // [d][code], padded
    const int tid = threadIdx.x;
    const int k0  = blockIdx.x * 64;

    // Load 64 codes x 64 dims, transpose into ts
#pragma unroll
    for (int i = 0; i < 4; i++) {
        int e = tid + 256 * i;        // 0..1023 float4 units
        int r = e >> 4;               // code 0..63
        int q = e & 15;               // float4 col
        float4 v = *reinterpret_cast<const float4*>(cb + (size_t)(k0 + r) * DIM + 4 * q);
        ts[4 * q + 0][r] = v.x;
        ts[4 * q + 1][r] = v.y;
        ts[4 * q + 2][r] = v.z;
        ts[4 * q + 3][r] = v.w;
    }
    __syncthreads();

    // nc_k = sum_d fl(c_d*c_d), strictly sequential (matches reference rounding)
    if (tid < 64) {
        float s = 0.f;
#pragma unroll
        for (int d = 0; d < DIM; d++)
            s = __fadd_rn(s, __fmul_rn(ts[d][tid], ts[d][tid]));
        d_cn[k0 + tid] = s;
    }

    // Write grouped-transposed rows: group g (16 codes), row d, 16 floats.
#pragma unroll
    for (int i = 0; i < 4; i++) {
        int e  = tid + 256 * i;       // 0..1023 float4 units
        int d  = e & 63;
        int r  = e >> 6;              // 0..15
        int g  = r >> 2;              // local group 0..3
        int c4 = r & 3;               // float4 within group
        float4 v = make_float4(ts[d][g * 16 + c4 * 4 + 0], ts[d][g * 16 + c4 * 4 + 1],
                               ts[d][g * 16 + c4 * 4 + 2], ts[d][g * 16 + c4 * 4 + 3]);
        *reinterpret_cast<float4*>(d_cbT + (size_t)((k0 >> 4) + g) * (DIM * 16)
                                   + d * 16 + c4 * 4) = v;
    }
}

// ---------------------------------------------------------------------------
// vq: codebook streamed L2->regs, x from shared, no per-tile syncs.
// Exact reference-rounded epilogue + argmin + gather.
// ---------------------------------------------------------------------------
__global__ void __launch_bounds__(THREADS, 2) vq_kernel(const float* __restrict__ ze,
                                                        const float* __restrict__ cb,
                                                        float* __restrict__ out) {
    extern __shared__ float smem[];
    float* xs2  = smem;                     // [64 d][4 s][8 nt][4]  32768 B
    float* cn_s = xs2 + DIM * 128;          // [8192]                32768 B
    float* nxs  = cn_s + KCODES;            // [64]                    256 B
    float* rb   = nxs + TN;                 // [64 n][16 kt]          4096 B
    int*   ri   = (int*)(rb + TN * 16);     // [64 n][16 kt]          4096 B
    int*   bx   = ri + TN * 16;             // [64]                    256 B

    const int tid = threadIdx.x;
    const int nt  = tid & 7;    // 8 point-groups of 8 points
    const int kt  = tid >> 3;   // 16 code-groups of 16 codes
    const int n0  = blockIdx.x * TN;
    const int b   = n0 >> 12;        // 4096 = H*W points per batch image
    const int hw0 = n0 & 4095;
    const float* zb = ze + (size_t)b * DIM * 4096 + hw0;

    // Fill xs2: point nl -> (nt,i), i=2s+h; dup both lanes of its pair slot.
    // Layout float offset: d*128 + s*32 + nt*4 + h*2.
#pragma unroll
    for (int it = 0; it < 32; it++) {
        int e  = tid + it * THREADS;   // 0..4095
        int nl = e & 63;
        int d  = e >> 6;
        float v = zb[(size_t)d * 4096 + nl];
        int nt_ = nl >> 3;
        int i   = nl & 7;
        int off = d * 128 + (i >> 1) * 32 + nt_ * 4 + (i & 1) * 2;
        xs2[off]     = v;
        xs2[off + 1] = v;
    }

    // Stage all code norms into shared (read once from L2).
    {
        const float4* src = reinterpret_cast<const float4*>(d_cn);
        float4* dst = reinterpret_cast<float4*>(cn_s);
#pragma unroll
        for (int i = 0; i < 16; i++)
            dst[tid + THREADS * i] = src[tid + THREADS * i];
    }
    __syncthreads();

    // nx per point: sequential sum of fl(x_d^2), no FMA contraction.
    if (tid < TN) {
        int nt_ = tid >> 3;
        int i   = tid & 7;
        const float* p = xs2 + (i >> 1) * 32 + nt_ * 4 + (i & 1) * 2;
        float s = 0.f;
#pragma unroll
        for (int d = 0; d < DIM; d++) {
            float v = p[d * 128];
            s = __fadd_rn(s, __fmul_rn(v, v));
        }
        nxs[tid] = s;
    }
    __syncthreads();

    float nxr[8];
#pragma unroll
    for (int i = 0; i < 8; i++) nxr[i] = nxs[8 * nt + i];

    float best[8];   // running min d2
    int   bi[8];
#pragma unroll
    for (int i = 0; i < 8; i++) { best[i] = 3.4e38f; bi[i] = 0; }

    const ulonglong2* xb = reinterpret_cast<const ulonglong2*>(xs2) + nt;

#pragma unroll 1
    for (int t = 0; t < NTILES; t++) {
        const int k0 = t * 256;
        // This thread's 16-code group: contiguous [64 d][16 floats] block.
        const ulonglong2* gp = reinterpret_cast<const ulonglong2*>(
            d_cbT + (size_t)(t * 16 + kt) * (DIM * 16));

        unsigned long long acc[8][8];   // 8 points x 8 code-pairs (f32x2)
#pragma unroll
        for (int i = 0; i < 8; i++)
#pragma unroll
            for (int j = 0; j < 8; j++) acc[i][j] = 0ULL;

        unsigned long long xq[8], cq[8];
        // preload d=0
        {
            ulonglong2 x0 = xb[0], x1 = xb[8], x2 = xb[16], x3 = xb[24];
            xq[0] = x0.x; xq[1] = x0.y; xq[2] = x1.x; xq[3] = x1.y;
            xq[4] = x2.x; xq[5] = x2.y; xq[6] = x3.x; xq[7] = x3.y;
            ulonglong2 c0 = gp[0], c1 = gp[1], c2 = gp[2], c3 = gp[3];
            cq[0] = c0.x; cq[1] = c0.y; cq[2] = c1.x; cq[3] = c1.y;
            cq[4] = c2.x; cq[5] = c2.y; cq[6] = c3.x; cq[7] = c3.y;
        }

        // m = sum_d x_d * c_d, sequential FMA ascending d; 1-deep reg prefetch.
        // d=63 overfetches d=64 (in-bounds: cn_s region / d_cbT pad), discarded.
#pragma unroll 4
        for (int d = 0; d < DIM; d++) {
            unsigned long long xn[8], cn2[8];
            {
                const ulonglong2* xp = xb + (d + 1) * 32;
                ulonglong2 x0 = xp[0], x1 = xp[8], x2 = xp[16], x3 = xp[24];
                xn[0] = x0.x; xn[1] = x0.y; xn[2] = x1.x; xn[3] = x1.y;
                xn[4] = x2.x; xn[5] = x2.y; xn[6] = x3.x; xn[7] = x3.y;
                const ulonglong2* cp = gp + (d + 1) * 4;
                ulonglong2 c0 = cp[0], c1 = cp[1], c2 = cp[2], c3 = cp[3];
                cn2[0] = c0.x; cn2[1] = c0.y; cn2[2] = c1.x; cn2[3] = c1.y;
                cn2[4] = c2.x; cn2[5] = c2.y; cn2[6] = c3.x; cn2[7] = c3.y;
            }
#pragma unroll
            for (int i = 0; i < 8; i++)
#pragma unroll
                for (int j = 0; j < 8; j++)
                    fma2(acc[i][j], xq[i], cq[j]);
#pragma unroll
            for (int q = 0; q < 8; q++) { xq[q] = xn[q]; cq[q] = cn2[q]; }
        }

        // Fold: d2 = fl(fl(nx - fl(2m)) + nc), ascending k, strict < (first-index ties)
#pragma unroll
        for (int j = 0; j < 8; j++) {
            int kk = k0 + 16 * kt + 2 * j;
            float2 cpair = *reinterpret_cast<const float2*>(&cn_s[kk]);
#pragma unroll
            for (int i = 0; i < 8; i++) {
                float lo, hi;
                unpack2(acc[i][j], lo, hi);
                float t0 = __fadd_rn(nxr[i], -__fmul_rn(2.0f, lo));
                float t1 = __fadd_rn(nxr[i], -__fmul_rn(2.0f, hi));
                float d0 = __fadd_rn(t0, cpair.x);
                float d1 = __fadd_rn(t1, cpair.y);
                if (d0 < best[i]) { best[i] = d0; bi[i] = kk; }
                if (d1 < best[i]) { best[i] = d1; bi[i] = kk + 1; }
            }
        }
    }

    __syncthreads();
    // Cross-thread (kt) reduction per point, lowest-index tie-break
#pragma unroll
    for (int i = 0; i < 8; i++) {
        int p = 8 * nt + i;
        rb[p * 16 + kt] = best[i];
        ri[p * 16 + kt] = bi[i];
    }
    __syncthreads();
    if (tid < TN) {
        float bv = 3.4e38f;
        int   bj = 0x7fffffff;
#pragma unroll
        for (int t = 0; t < 16; t++) {
            float v  = rb[tid * 16 + t];
            int   ix = ri[tid * 16 + t];
            if (v < bv || (v == bv && ix < bj)) { bv = v; bj = ix; }
        }
        bx[tid] = bj;
    }
    __syncthreads();

    // Gather codebook rows; writes coalesced along nl
    float* ob = out + (size_t)b * DIM * 4096 + hw0;
#pragma unroll
    for (int it = 0; it < (DIM * TN) / THREADS; it++) {
        int e = tid + it * THREADS;
        int nl = e & 63;
        int d  = e >> 6;
        ob[(size_t)d * 4096 + nl] = cb[(size_t)bx[nl] * DIM + d];
    }
}

extern "C" void kernel_launch(void* const* d_in, const int* in_sizes, int n_in,
                              void* d_out, int out_size) {
    const float* ze = (const float*)d_in[0];   // [8,64,64,64] f32
    const float* cb = (const float*)d_in[1];   // [8192,64] f32
    float* out = (float*)d_out;                // [8,64,64,64] f32

    const int smem_bytes = (DIM * 128 + KCODES + TN + TN * 16) * 4 +
                           TN * 16 * 4 + TN * 4;   // 73472 B

    cudaFuncSetAttribute(vq_kernel, cudaFuncAttributeMaxDynamicSharedMemorySize,
                         smem_bytes);

    prep_kernel<<<KCODES / 64, 256>>>(cb);
    vq_kernel<<<NPTS / TN, THREADS, smem_bytes>>>(ze, cb, out);
}

// round 5
// speedup vs baseline: 1.1226x; 1.1226x over previous
#include <cuda_runtime.h>
#include <cstdint>

// Problem constants (fixed shapes from reference)
#define DIM      64
#define KCODES   8192
#define NPTS     32768
#define TN       64          // points per block
#define TKT      64          // codes per k-tile
#define NTILES   (KCODES / TKT)
#define THREADS  128

// Codebook pre-transposed per tile: d_cbT[t][d][c] = cb[t*64 + c][d]
__device__ float d_cbT[DIM * KCODES];
// ||c_k||^2 with reference rounding (sequential mul-then-add, no FMA)
__device__ float d_cn[KCODES];

__device__ __forceinline__ void fma2(unsigned long long& d,
                                     unsigned long long a,
                                     unsigned long long b) {
    asm("fma.rn.f32x2 %0, %1, %2, %3;" : "=l"(d) : "l"(a), "l"(b), "l"(d));
}
__device__ __forceinline__ unsigned long long pack2(float x) {
    unsigned long long r;
    asm("mov.b64 %0, {%1, %1};" : "=l"(r) : "f"(x));
    return r;
}
__device__ __forceinline__ void unpack2(unsigned long long v, float& lo, float& hi) {
    asm("mov.b64 {%0, %1}, %2;" : "=f"(lo), "=f"(hi) : "l"(v));
}

// ---------------------------------------------------------------------------
// prep: transpose codebook into per-tile [d][64] blocks + compute d_cn.
// One block per 64-code tile. Tiny (2 MB moved once).
// ---------------------------------------------------------------------------
__global__ void __launch_bounds__(256) prep_kernel(const float* __restrict__ cb) {
    __shared__ float ts[DIM][65];   // [d][code], padded
    const int tid = threadIdx.x;
    const int k0  = blockIdx.x * 64;

    // Load 64 codes x 64 dims, transpose into ts
#pragma unroll
    for (int i = 0; i < 4; i++) {
        int e = tid + 256 * i;        // 0..1023 float4 units
        int r = e >> 4;               // code 0..63
        int q = e & 15;               // float4 col
        float4 v = *reinterpret_cast<const float4*>(cb + (size_t)(k0 + r) * DIM + 4 * q);
        ts[4 * q + 0][r] = v.x;
        ts[4 * q + 1][r] = v.y;
        ts[4 * q + 2][r] = v.z;
        ts[4 * q + 3][r] = v.w;
    }
    __syncthreads();

    // nc_k = sum_d fl(c_d*c_d), strictly sequential (matches reference rounding)
    if (tid < 64) {
        float s = 0.f;
#pragma unroll
        for (int d = 0; d < DIM; d++)
            s = __fadd_rn(s, __fmul_rn(ts[d][tid], ts[d][tid]));
        d_cn[k0 + tid] = s;
    }

    // Write transposed tile: dst[t*4096 + d*64 + c]
    float* dst = d_cbT + (size_t)blockIdx.x * (DIM * 64);
#pragma unroll
    for (int i = 0; i < 4; i++) {
        int e = tid + 256 * i;        // 0..1023 float4 units
        int d = e >> 4;
        int q = e & 15;
        float4 v = make_float4(ts[d][4 * q + 0], ts[d][4 * q + 1],
                               ts[d][4 * q + 2], ts[d][4 * q + 3]);
        *reinterpret_cast<float4*>(dst + d * 64 + 4 * q) = v;
    }
}

// ---------------------------------------------------------------------------
// vq: small per-thread tile (4 pts x 8 codes), 5 blocks/SM for TLP.
// Exact reference-rounded epilogue + argmin + gather.
// ---------------------------------------------------------------------------
__global__ void __launch_bounds__(THREADS, 5) vq_kernel(const float* __restrict__ ze,
                                                        const float* __restrict__ cb,
                                                        float* __restrict__ out) {
    extern __shared__ float smem[];
    float* xs   = smem;                     // [64 d][64 n]        16384 B
    float* cs   = xs + DIM * TN;            // [64 d][64 c]        16384 B
    float* cn_s = cs + DIM * TKT;           // [64]                  256 B
    float* nxs  = cn_s + TKT;               // [64]                  256 B
    int*   bx   = (int*)(nxs + TN);         // [64]                  256 B
    // after main loop, cs is dead -> reuse as reduction buffers
    float* rb   = cs;                       // [64 n][8 kt]
    int*   ri   = (int*)(cs + TN * 8);      // [64 n][8 kt]

    const int tid = threadIdx.x;
    const int nt  = tid & 15;   // 16 point-groups of 4 points
    const int kt  = tid >> 4;   // 8 code-groups of 8 codes
    const int n0  = blockIdx.x * TN;
    const int b   = n0 >> 12;        // 4096 = H*W points per batch image
    const int hw0 = n0 & 4095;
    const float* zb = ze + (size_t)b * DIM * 4096 + hw0;

    // Load x tile: xs[d][nl], coalesced along nl (w-dim contiguous).
#pragma unroll
    for (int it = 0; it < (DIM * TN) / THREADS; it++) {
        int e  = tid + it * THREADS;
        int nl = e & 63;
        int d  = e >> 6;
        xs[d * 64 + nl] = zb[(size_t)d * 4096 + nl];
    }
    __syncthreads();

    // nx per point: sequential sum of fl(x_d^2), no FMA contraction.
    if (tid < TN) {
        float s = 0.f;
#pragma unroll
        for (int d = 0; d < DIM; d++) {
            float v = xs[d * 64 + tid];
            s = __fadd_rn(s, __fmul_rn(v, v));
        }
        nxs[tid] = s;
    }
    __syncthreads();

    float nxr[4];
#pragma unroll
    for (int i = 0; i < 4; i++) nxr[i] = nxs[4 * nt + i];

    float best[4];   // running min d2
    int   bi[4];
#pragma unroll
    for (int i = 0; i < 4; i++) { best[i] = 3.4e38f; bi[i] = 0; }

#pragma unroll 1
    for (int t = 0; t < NTILES; t++) {
        const int k0 = t * TKT;
        __syncthreads();   // protect cs/cn_s from previous tile's readers

        // Tile fill: identity float4 copy (prep already transposed per tile).
        {
            const float4* src = reinterpret_cast<const float4*>(
                d_cbT + (size_t)t * (DIM * TKT));
            float4* dst = reinterpret_cast<float4*>(cs);
#pragma unroll
            for (int i = 0; i < (DIM * TKT / 4) / THREADS; i++)
                dst[tid + THREADS * i] = src[tid + THREADS * i];
            if (tid < TKT) cn_s[tid] = d_cn[k0 + tid];
        }
        __syncthreads();

        unsigned long long acc[4][4];   // 4 points x 4 code-pairs (f32x2)
#pragma unroll
        for (int i = 0; i < 4; i++)
#pragma unroll
            for (int j = 0; j < 4; j++) acc[i][j] = 0ULL;

        // m = sum_d x_d * c_d, sequential FMA in ascending d
#pragma unroll 8
        for (int d = 0; d < DIM; d++) {
            float4 xv = *reinterpret_cast<const float4*>(&xs[d * 64 + 4 * nt]);
            unsigned long long xq[4];
            xq[0] = pack2(xv.x); xq[1] = pack2(xv.y);
            xq[2] = pack2(xv.z); xq[3] = pack2(xv.w);
            const ulonglong2* cp =
                reinterpret_cast<const ulonglong2*>(&cs[d * 64 + 8 * kt]);
            ulonglong2 c01 = cp[0];
            ulonglong2 c23 = cp[1];
            unsigned long long cq[4] = {c01.x, c01.y, c23.x, c23.y};
#pragma unroll
            for (int i = 0; i < 4; i++)
#pragma unroll
                for (int j = 0; j < 4; j++)
                    fma2(acc[i][j], xq[i], cq[j]);
        }

        // Fold: d2 = fl(fl(nx - fl(2m)) + nc), ascending k, strict < (first-index ties)
#pragma unroll
        for (int j = 0; j < 4; j++) {
            int kk = 8 * kt + 2 * j;
            float2 cpair = *reinterpret_cast<const float2*>(&cn_s[kk]);
            int kg = k0 + kk;
#pragma unroll
            for (int i = 0; i < 4; i++) {
                float lo, hi;
                unpack2(acc[i][j], lo, hi);
                float t0 = __fadd_rn(nxr[i], -__fmul_rn(2.0f, lo));
                float t1 = __fadd_rn(nxr[i], -__fmul_rn(2.0f, hi));
                float d0 = __fadd_rn(t0, cpair.x);
                float d1 = __fadd_rn(t1, cpair.y);
                if (d0 < best[i]) { best[i] = d0; bi[i] = kg; }
                if (d1 < best[i]) { best[i] = d1; bi[i] = kg + 1; }
            }
        }
    }

    __syncthreads();
    // Cross-thread (kt) reduction per point, lowest-index tie-break (rb/ri alias cs)
#pragma unroll
    for (int i = 0; i < 4; i++) {
        int p = 4 * nt + i;
        rb[p * 8 + kt] = best[i];
        ri[p * 8 + kt] = bi[i];
    }
    __syncthreads();
    if (tid < TN) {
        float bv = 3.4e38f;
        int   bj = 0x7fffffff;
#pragma unroll
        for (int t = 0; t < 8; t++) {
            float v  = rb[tid * 8 + t];
            int   ix = ri[tid * 8 + t];
            if (v < bv || (v == bv && ix < bj)) { bv = v; bj = ix; }
        }
        bx[tid] = bj;
    }
    __syncthreads();

    // Gather codebook rows; writes coalesced along nl
    float* ob = out + (size_t)b * DIM * 4096 + hw0;
#pragma unroll
    for (int it = 0; it < (DIM * TN) / THREADS; it++) {
        int e  = tid + it * THREADS;
        int nl = e & 63;
        int d  = e >> 6;
        ob[(size_t)d * 4096 + nl] = cb[(size_t)bx[nl] * DIM + d];
    }
}

extern "C" void kernel_launch(void* const* d_in, const int* in_sizes, int n_in,
                              void* d_out, int out_size) {
    const float* ze = (const float*)d_in[0];   // [8,64,64,64] f32
    const float* cb = (const float*)d_in[1];   // [8192,64] f32
    float* out = (float*)d_out;                // [8,64,64,64] f32

    const int smem_bytes = (DIM * TN + DIM * TKT + TKT + TN + TN) * 4;  // 33536 B

    cudaFuncSetAttribute(vq_kernel, cudaFuncAttributeMaxDynamicSharedMemorySize,
                         smem_bytes);

    prep_kernel<<<KCODES / 64, 256>>>(cb);
    vq_kernel<<<NPTS / TN, THREADS, smem_bytes>>>(ze, cb, out);
}

// round 7
// speedup vs baseline: 2.8828x; 2.5680x over previous
#include <cuda_runtime.h>
#include <cuda_bf16.h>
#include <cstdint>

#define DIM     64
#define KC      8192
#define NP      32768
#define KS      192          // split-K: [hi|lo|hi] x [hi|hi|lo]
#define MT      128          // points per CTA
#define NT      64           // codes per tile
#define NTILES  (KC / NT)    // 128
#define GT      256
#define LDA     200          // padded bf16 row stride (400 B)

__device__ __align__(16) __nv_bfloat16 d_A[NP * KS];   // 12.6 MB
__device__ __align__(16) __nv_bfloat16 d_B[KC * KS];   // 3.1 MB
__device__ float d_cn[KC];
__device__ int2  d_cand[NP];
__device__ int   d_idx[NP];

// SMEM layout (gemm): A 128x400B | B 2x 64x400B | cn 2x 256B
#define S_A    0
#define S_B    51200
#define S_CN   102400
#define SMEM_G 102912

// ---------------------------------------------------------------------------
// helpers (all generic PTX, sm_80+)
// ---------------------------------------------------------------------------
__device__ __forceinline__ uint32_t smem_u32(const void* p) {
    uint32_t a;
    asm("{ .reg .u64 t; cvta.to.shared.u64 t, %1; cvt.u32.u64 %0, t; }"
        : "=r"(a) : "l"(p));
    return a;
}
__device__ __forceinline__ void cpa16(uint32_t dst, const void* src) {
    asm volatile("cp.async.cg.shared.global [%0], [%1], 16;" :: "r"(dst), "l"(src)
                 : "memory");
}
__device__ __forceinline__ void cpa4(uint32_t dst, const void* src) {
    asm volatile("cp.async.ca.shared.global [%0], [%1], 4;" :: "r"(dst), "l"(src)
                 : "memory");
}
#define CP_COMMIT() asm volatile("cp.async.commit_group;" ::: "memory")
#define CP_WAIT1()  asm volatile("cp.async.wait_group 1;" ::: "memory")

__device__ __forceinline__ void ldm_x4(uint32_t* r, uint32_t addr) {
    asm volatile("ldmatrix.sync.aligned.m8n8.x4.shared.b16 {%0,%1,%2,%3}, [%4];"
                 : "=r"(r[0]), "=r"(r[1]), "=r"(r[2]), "=r"(r[3]) : "r"(addr));
}
__device__ __forceinline__ void mma_bf16(float* d, const uint32_t* a,
                                         uint32_t b0, uint32_t b1) {
    asm volatile(
        "mma.sync.aligned.m16n8k16.row.col.f32.bf16.bf16.f32 "
        "{%0,%1,%2,%3}, {%4,%5,%6,%7}, {%8,%9}, {%0,%1,%2,%3};"
        : "+f"(d[0]), "+f"(d[1]), "+f"(d[2]), "+f"(d[3])
        : "r"(a[0]), "r"(a[1]), "r"(a[2]), "r"(a[3]), "r"(b0), "r"(b1));
}

// ---------------------------------------------------------------------------
// prep kernels
// ---------------------------------------------------------------------------
__global__ void __launch_bounds__(256) prep_cn(const float* __restrict__ cb) {
    int k = blockIdx.x * 256 + threadIdx.x;
    const float* row = cb + (size_t)k * DIM;
    float s = 0.f;
#pragma unroll
    for (int i = 0; i < DIM; i++)
        s = __fadd_rn(s, __fmul_rn(row[i], row[i]));
    d_cn[k] = s;
}

// A' rows: [hi(d0..63) | lo | hi]
__global__ void __launch_bounds__(128) prep_A(const float* __restrict__ ze) {
    __shared__ float xs[DIM * 64];
    const int tid = threadIdx.x;
    const int n0  = blockIdx.x * 64;
    const int b   = n0 >> 12;
    const int hw0 = n0 & 4095;
    const float* zb = ze + (size_t)b * DIM * 4096 + hw0;
#pragma unroll
    for (int it = 0; it < 32; it++) {
        int e = tid + it * 128;
        int nl = e & 63, d = e >> 6;
        xs[d * 64 + nl] = zb[(size_t)d * 4096 + nl];
    }
    __syncthreads();
    uint32_t* out = (uint32_t*)d_A;
#pragma unroll
    for (int i = 0; i < 48; i++) {
        int e   = tid + i * 128;      // 0..6143
        int nl  = e / 96;
        int c   = e % 96;             // uint col (2 bf16)
        int blk = c >> 5;             // 0:hi 1:lo 2:hi
        int d0  = (c & 31) * 2;
        float v0 = xs[d0 * 64 + nl], v1 = xs[(d0 + 1) * 64 + nl];
        __nv_bfloat16 h0 = __float2bfloat16(v0);
        __nv_bfloat16 h1 = __float2bfloat16(v1);
        if (blk == 1) {
            h0 = __float2bfloat16(v0 - __bfloat162float(h0));
            h1 = __float2bfloat16(v1 - __bfloat162float(h1));
        }
        out[(size_t)(n0 + nl) * 96 + c] =
            (uint32_t)__bfloat16_as_ushort(h0) |
            ((uint32_t)__bfloat16_as_ushort(h1) << 16);
    }
}

// B' rows: [hi | hi | lo]
__global__ void __launch_bounds__(256) prep_B(const float* __restrict__ cb) {
    int idx = blockIdx.x * 256 + threadIdx.x;   // 0 .. 8192*96-1
    int row = idx / 96;
    int c   = idx % 96;
    int blk = c >> 5;                 // 0:hi 1:hi 2:lo
    int d0  = (c & 31) * 2;
    float v0 = cb[(size_t)row * 64 + d0], v1 = cb[(size_t)row * 64 + d0 + 1];
    __nv_bfloat16 h0 = __float2bfloat16(v0);
    __nv_bfloat16 h1 = __float2bfloat16(v1);
    if (blk == 2) {
        h0 = __float2bfloat16(v0 - __bfloat162float(h0));
        h1 = __float2bfloat16(v1 - __bfloat162float(h1));
    }
    ((uint32_t*)d_B)[(size_t)row * 96 + c] =
        (uint32_t)__bfloat16_as_ushort(h0) | ((uint32_t)__bfloat16_as_ushort(h1) << 16);
}

// ---------------------------------------------------------------------------
// GEMM (mma.sync bf16) + fused top-2 epilogue
// ---------------------------------------------------------------------------
__device__ __forceinline__ void load_B_tile(uint32_t sb, int t, int buf, int tid) {
#pragma unroll
    for (int i = 0; i < 6; i++) {
        int e = tid + GT * i;         // 0..1535
        int row = e / 24, c = e % 24;
        cpa16(sb + S_B + buf * 25600 + row * 400 + c * 16,
              d_B + (size_t)(t * NT + row) * KS + c * 8);
    }
    if (tid < NT)
        cpa4(sb + S_CN + buf * 256 + tid * 4, d_cn + t * NT + tid);
}

__global__ void __launch_bounds__(GT, 2) gemm_kernel() {
    extern __shared__ char smem[];
    const uint32_t sb = smem_u32(smem);
    const int tid = threadIdx.x;
    const int wid = tid >> 5;
    const int l   = tid & 31;
    const int wm  = wid & 3;          // M-warp 0..3 (32 rows each)
    const int wn  = wid >> 2;         // N-warp 0..1 (32 cols each)
    const int m0  = blockIdx.x * MT;

    // A tile (once, grouped with B0)
#pragma unroll
    for (int i = 0; i < 12; i++) {
        int e = tid + GT * i;         // 0..3071
        int row = e / 24, c = e % 24;
        cpa16(sb + S_A + row * 400 + c * 16, d_A + (size_t)(m0 + row) * KS + c * 8);
    }
    load_B_tile(sb, 0, 0, tid);
    CP_COMMIT();
    load_B_tile(sb, 1, 1, tid);
    CP_COMMIT();
    CP_WAIT1();
    __syncthreads();                  // A + B0 ready

    // ldmatrix per-thread base addresses
    const uint32_t aA0 = sb + S_A + (wm * 32 + (l & 15)) * 400 + (l >> 4) * 16;
    const uint32_t aA1 = aA0 + 16 * 400;
    const uint32_t bRow = (uint32_t)(wn * 32 + (l & 7) + ((l >> 3) & 1) * 8);
    const uint32_t aB0 = sb + S_B + bRow * 400 + (l >> 4) * 16;
    const uint32_t aB1 = aB0 + 16 * 400;

    float b1[4], b2[4];
    int   i1[4], i2[4];
#pragma unroll
    for (int s = 0; s < 4; s++) { b1[s] = 3.4e38f; b2[s] = 3.4e38f; i1[s] = 0; i2[s] = 0; }

#pragma unroll 1
    for (int t = 0; t < NTILES; t++) {
        const int buf = t & 1;
        const uint32_t boff = (uint32_t)buf * 25600;

        float acc[2][4][4];
#pragma unroll
        for (int mt = 0; mt < 2; mt++)
#pragma unroll
            for (int j = 0; j < 4; j++)
#pragma unroll
                for (int q = 0; q < 4; q++) acc[mt][j][q] = 0.f;

#pragma unroll
        for (int ks = 0; ks < 12; ks++) {
            const uint32_t koff = (uint32_t)(ks * 32);   // 16 bf16 = 32 B
            uint32_t ra0[4], ra1[4], rb01[4], rb23[4];
            ldm_x4(ra0,  aA0 + koff);
            ldm_x4(ra1,  aA1 + koff);
            ldm_x4(rb01, aB0 + boff + koff);
            ldm_x4(rb23, aB1 + boff + koff);
            mma_bf16(acc[0][0], ra0, rb01[0], rb01[2]);
            mma_bf16(acc[0][1], ra0, rb01[1], rb01[3]);
            mma_bf16(acc[0][2], ra0, rb23[0], rb23[2]);
            mma_bf16(acc[0][3], ra0, rb23[1], rb23[3]);
            mma_bf16(acc[1][0], ra1, rb01[0], rb01[2]);
            mma_bf16(acc[1][1], ra1, rb01[1], rb01[3]);
            mma_bf16(acc[1][2], ra1, rb23[0], rb23[2]);
            mma_bf16(acc[1][3], ra1, rb23[1], rb23[3]);
        }

        // epilogue: score = nc - 2*m; top-2 per row-slot
        const float* cnp = (const float*)(smem + S_CN + buf * 256);
        const int kb0 = t * NT;
#pragma unroll
        for (int mt = 0; mt < 2; mt++) {
#pragma unroll
            for (int j = 0; j < 4; j++) {
                int cbl = wn * 32 + j * 8 + 2 * (l & 3);
                float c0 = cnp[cbl], c1 = cnp[cbl + 1];
                int kk = kb0 + cbl;
                int s0 = mt * 2, s1 = mt * 2 + 1;
                float v0 = fmaf(-2.f, acc[mt][j][0], c0);
                float v1 = fmaf(-2.f, acc[mt][j][1], c1);
                float v2 = fmaf(-2.f, acc[mt][j][2], c0);
                float v3 = fmaf(-2.f, acc[mt][j][3], c1);
                if (v0 < b1[s0]) { b2[s0] = b1[s0]; i2[s0] = i1[s0]; b1[s0] = v0; i1[s0] = kk; }
                else if (v0 < b2[s0]) { b2[s0] = v0; i2[s0] = kk; }
                if (v1 < b1[s0]) { b2[s0] = b1[s0]; i2[s0] = i1[s0]; b1[s0] = v1; i1[s0] = kk + 1; }
                else if (v1 < b2[s0]) { b2[s0] = v1; i2[s0] = kk + 1; }
                if (v2 < b1[s1]) { b2[s1] = b1[s1]; i2[s1] = i1[s1]; b1[s1] = v2; i1[s1] = kk; }
                else if (v2 < b2[s1]) { b2[s1] = v2; i2[s1] = kk; }
                if (v3 < b1[s1]) { b2[s1] = b1[s1]; i2[s1] = i1[s1]; b1[s1] = v3; i1[s1] = kk + 1; }
                else if (v3 < b2[s1]) { b2[s1] = v3; i2[s1] = kk + 1; }
            }
        }

        __syncthreads();                       // everyone done reading buf
        if (t + 2 < NTILES) load_B_tile(sb, t + 2, buf, tid);
        CP_COMMIT();
        CP_WAIT1();                            // B(t+1) ready
        __syncthreads();
    }

    // quad merge (lanes sharing l>>2 hold same rows)
#pragma unroll
    for (int s = 0; s < 4; s++) {
#pragma unroll
        for (int off = 1; off <= 2; off <<= 1) {
            float t1 = __shfl_xor_sync(0xFFFFFFFFu, b1[s], off);
            int   j1 = __shfl_xor_sync(0xFFFFFFFFu, i1[s], off);
            float t2 = __shfl_xor_sync(0xFFFFFFFFu, b2[s], off);
            int   j2 = __shfl_xor_sync(0xFFFFFFFFu, i2[s], off);
            if (t1 < b1[s]) {
                float nb2 = fminf(b1[s], t2);
                int   ni2 = (t2 < b1[s]) ? j2 : i1[s];
                b1[s] = t1; i1[s] = j1; b2[s] = nb2; i2[s] = ni2;
            } else if (t1 < b2[s]) {
                b2[s] = t1; i2[s] = j1;
            }
        }
    }

    // cross-N-warp merge via smem (reuse B region)
    float4* red = (float4*)(smem + S_B);       // [128 rows][2 wn]
    if ((l & 3) == 0) {
#pragma unroll
        for (int s = 0; s < 4; s++) {
            int row = wm * 32 + (s >> 1) * 16 + (s & 1) * 8 + (l >> 2);
            red[row * 2 + wn] = make_float4(b1[s], __int_as_float(i1[s]),
                                            b2[s], __int_as_float(i2[s]));
        }
    }
    __syncthreads();
    if (tid < MT) {
        float4 A4 = red[tid * 2 + 0];
        float4 B4 = red[tid * 2 + 1];
        float s1 = A4.x, s2 = A4.z;
        int   k1 = __float_as_int(A4.y), k2 = __float_as_int(A4.w);
        float t1 = B4.x, t2 = B4.z;
        int   j1 = __float_as_int(B4.y), j2 = __float_as_int(B4.w);
        if (t1 < s1) {
            float n2 = fminf(s1, t2);
            int   n2i = (t2 < s1) ? j2 : k1;
            s1 = t1; k1 = j1; s2 = n2; k2 = n2i;
        } else if (t1 < s2) {
            s2 = t1; k2 = j1;
        }
        d_cand[m0 + tid] = make_int2(k1, k2);
    }
}

// ---------------------------------------------------------------------------
// Exact rescore of the 2 candidates with reference-identical rounding
// ---------------------------------------------------------------------------
__global__ void __launch_bounds__(256) rescore(const float* __restrict__ ze,
                                               const float* __restrict__ cb) {
    int n = blockIdx.x * 256 + threadIdx.x;
    int b = n >> 12, hw = n & 4095;
    float x[DIM];
#pragma unroll
    for (int d = 0; d < DIM; d++)
        x[d] = ze[(size_t)(b * DIM + d) * 4096 + hw];
    float nx = 0.f;
#pragma unroll
    for (int d = 0; d < DIM; d++)
        nx = __fadd_rn(nx, __fmul_rn(x[d], x[d]));
    int2 cd = d_cand[n];
    int ka = min(cd.x, cd.y), kb = max(cd.x, cd.y);
    const float* ra = cb + (size_t)ka * DIM;
    const float* rb = cb + (size_t)kb * DIM;
    float ma = 0.f, mb = 0.f;
#pragma unroll
    for (int d = 0; d < DIM; d++) {
        ma = __fmaf_rn(x[d], ra[d], ma);
        mb = __fmaf_rn(x[d], rb[d], mb);
    }
    float d2a = __fadd_rn(__fadd_rn(nx, -__fmul_rn(2.0f, ma)), d_cn[ka]);
    float d2b = __fadd_rn(__fadd_rn(nx, -__fmul_rn(2.0f, mb)), d_cn[kb]);
    d_idx[n] = (d2b < d2a) ? kb : ka;   // strict: tie -> lower index
}

// ---------------------------------------------------------------------------
// Gather z_q
// ---------------------------------------------------------------------------
__global__ void __launch_bounds__(128) gather(const float* __restrict__ cb,
                                              float* __restrict__ out) {
    __shared__ int bx[64];
    const int tid = threadIdx.x;
    const int n0  = blockIdx.x * 64;
    const int b   = n0 >> 12;
    const int hw0 = n0 & 4095;
    if (tid < 64) bx[tid] = d_idx[n0 + tid];
    __syncthreads();
    float* ob = out + (size_t)b * DIM * 4096 + hw0;
#pragma unroll
    for (int it = 0; it < 32; it++) {
        int e = tid + it * 128;
        int nl = e & 63, d = e >> 6;
        ob[(size_t)d * 4096 + nl] = cb[(size_t)bx[nl] * DIM + d];
    }
}

extern "C" void kernel_launch(void* const* d_in, const int* in_sizes, int n_in,
                              void* d_out, int out_size) {
    const float* ze = (const float*)d_in[0];   // [8,64,64,64] f32
    const float* cb = (const float*)d_in[1];   // [8192,64] f32
    float* out = (float*)d_out;

    cudaFuncSetAttribute(gemm_kernel, cudaFuncAttributeMaxDynamicSharedMemorySize,
                         SMEM_G);

    prep_cn<<<KC / 256, 256>>>(cb);
    prep_A<<<NP / 64, 128>>>(ze);
    prep_B<<<(KC * 96) / 256, 256>>>(cb);
    gemm_kernel<<<NP / MT, GT, SMEM_G>>>();
    rescore<<<NP / 256, 256>>>(ze, cb);
    gather<<<NP / 64, 128>>>(cb, out);
}